// round 7
// baseline (speedup 1.0000x reference)
#include <cuda_runtime.h>
#include <cstdint>

#define N_NODES 2048
#define N_EDGES 8192
#define EDGE_DIM 10
#define EH 32
#define HID 160
#define COL_B2 (EH*HID)              // 5120
#define COL_ROOT (EH*HID + HID)      // 5280
#define NCOLS (EH*HID + HID + HID)   // 5440

// k-permutation within 8-blocks: orig k%8 = t(0..3) -> 2t ; t+4 -> 2t+1
__host__ __device__ __forceinline__ int kpos(int k) {
    return (k & ~7) | ((k & 3) << 1) | ((k & 4) >> 2);
}

// ---------------- device scratch ----------------
__device__ float g_T[N_NODES * NCOLS];    // tf32 bits, cols kpos-permuted
__device__ float g_B[2][NCOLS * HID];     // tf32 bits, rows kpos-permuted
__device__ float g_h[2][N_EDGES * EH];
__device__ float g_out[N_NODES * HID];    // split-K accumulator (fp32)
__device__ float g_xb[2][N_NODES * HID];  // layer ping-pong (fp32)
__device__ int   g_src[N_EDGES];
__device__ int   g_csr_off[N_NODES + 1];  // CSR by dst
__device__ int   g_csr_edge[N_EDGES];

__device__ __forceinline__ uint32_t f2tf32(float f) {
    uint32_t u;
    asm("cvt.rna.tf32.f32 %0, %1;" : "=r"(u) : "f"(f));
    return u;
}

// =====================================================================
// Preprocessing (one block): int64-detect, decode, CSR by dst.
// =====================================================================
__global__ __launch_bounds__(1024) void prep_kernel(const void* __restrict__ eiraw) {
    __shared__ int s_flag;
    __shared__ int s_cd[N_NODES];
    __shared__ int s_a[N_NODES];
    __shared__ int s_b[N_NODES];
    int t = threadIdx.x;

    for (int i = t; i < N_NODES; i += 1024) s_cd[i] = 0;
    if (t == 0) s_flag = 0;
    __syncthreads();

    const int* raw = (const int*)eiraw;
    int f = 0;
    for (int i = t; i < N_EDGES; i += 1024)
        if (raw[2 * i + 1] != 0) f = 1;
    if (f) atomicOr(&s_flag, 1);
    __syncthreads();
    int flag = s_flag;

    int es[8], ed[8];
    #pragma unroll
    for (int j = 0; j < 8; j++) {
        int e = t + 1024 * j;
        if (flag) {
            es[j] = raw[e]; ed[j] = raw[N_EDGES + e];
        } else {
            const long long* p = (const long long*)eiraw;
            es[j] = (int)p[e]; ed[j] = (int)p[N_EDGES + e];
        }
        atomicAdd(&s_cd[ed[j]], 1);
        g_src[e] = es[j];
    }
    __syncthreads();

    for (int i = t; i < N_NODES; i += 1024) s_a[i] = s_cd[i];
    __syncthreads();

    int* pa = s_a; int* pb = s_b;
    for (int d = 1; d < N_NODES; d <<= 1) {
        for (int i = t; i < N_NODES; i += 1024)
            pb[i] = pa[i] + (i >= d ? pa[i - d] : 0);
        __syncthreads();
        int* tmp = pa; pa = pb; pb = tmp;
    }
    for (int i = t; i < N_NODES; i += 1024) {
        int off = (i == 0) ? 0 : pa[i - 1];
        g_csr_off[i] = off;
        pb[i] = off;
    }
    if (t == 0) g_csr_off[N_NODES] = N_EDGES;
    __syncthreads();

    #pragma unroll
    for (int j = 0; j < 8; j++) {
        int e = t + 1024 * j;
        int pos = atomicAdd(&pb[ed[j]], 1);
        g_csr_edge[pos] = e;
    }
}

// =====================================================================
// Params: build g_B (tf32, row-permuted) both slots + edge MLP h both
// slots + zero g_out.
// =====================================================================
#define GB_BLOCKS (NCOLS * HID / 256)                // 3400
#define H_BLOCKS  (N_EDGES / 8)                      // 1024
#define Z_BLOCKS  (N_NODES * HID / 256)              // 1280

__global__ __launch_bounds__(256) void params_kernel(
        const float* __restrict__ w2a, const float* __restrict__ b2a,
        const float* __restrict__ roota,
        const float* __restrict__ w2b, const float* __restrict__ b2b,
        const float* __restrict__ rootb,
        const float* __restrict__ ea,
        const float* __restrict__ w1a, const float* __restrict__ b1a,
        const float* __restrict__ w1b, const float* __restrict__ b1b) {
    __shared__ float sw[EDGE_DIM * EH];
    __shared__ float sb[EH];
    int b = blockIdx.x;
    int t = threadIdx.x;

    if (b < 2 * GB_BLOCKS) {
        int slot = (b >= GB_BLOCKS);
        const float* w2   = slot ? w2b : w2a;
        const float* b2   = slot ? b2b : b2a;
        const float* root = slot ? rootb : roota;
        int idx = (b - slot * GB_BLOCKS) * 256 + t;
        int c = idx / HID;
        int o = idx % HID;
        float v;
        if (c < COL_B2)         v = w2[c * HID + o];
        else if (c < COL_ROOT)  v = b2[(c - COL_B2) * HID + o];
        else                    v = root[(c - COL_ROOT) * HID + o];
        g_B[slot][kpos(c) * HID + o] = __uint_as_float(f2tf32(v));
    } else if (b < 2 * GB_BLOCKS + 2 * H_BLOCKS) {
        int bb = b - 2 * GB_BLOCKS;
        int slot = (bb >= H_BLOCKS);
        const float* w1 = slot ? w1b : w1a;
        const float* b1 = slot ? b1b : b1a;
        for (int i = t; i < EDGE_DIM * EH; i += 256) sw[i] = w1[i];
        if (t < EH) sb[t] = b1[t];
        __syncthreads();
        int j  = t & 31;
        int e  = (bb - slot * H_BLOCKS) * 8 + (t >> 5);
        float acc = sb[j];
        #pragma unroll
        for (int d = 0; d < EDGE_DIM; d++)
            acc += ea[e * EDGE_DIM + d] * sw[d * EH + j];
        g_h[slot][e * EH + j] = fmaxf(acc, 0.0f);
    } else {
        int idx = (b - 2 * GB_BLOCKS - 2 * H_BLOCKS) * 256 + t;
        g_out[idx] = 0.0f;
    }
}

// =====================================================================
// Aggregation: CSR-by-dst, one block/node. Chunked staging: all <=32
// edges' x-rows + h-rows loaded in parallel, ONE sync, then accumulate.
// =====================================================================
#define ECAP 32

__global__ __launch_bounds__(256) void agg_kernel(const float* __restrict__ xin,
                                                  int xsel, int slot) {
    __shared__ float xs[ECAP][HID];   // 20 KB
    __shared__ float hs[ECAP][EH];    // 4 KB
    const float* __restrict__ X = (xsel < 0) ? xin : g_xb[xsel];
    int n = blockIdx.x;
    int t = threadIdx.x;
    int beg = g_csr_off[n];
    int end = g_csr_off[n + 1];
    float inv = 1.0f / fmaxf((float)(end - beg), 1.0f);

    float acc[20];
    int kk[20], ii[20];
    #pragma unroll
    for (int r = 0; r < 20; r++) {
        int c = t + 256 * r;          // < 5120
        kk[r] = c / HID;
        ii[r] = c % HID;
        acc[r] = 0.0f;
    }
    float acc2 = 0.0f;

    for (int cb = beg; cb < end; cb += ECAP) {
        int m = min(end - cb, ECAP);
        // stage all x rows of this chunk: m*40 float4, in parallel
        for (int i = t; i < m * 40; i += 256) {
            int j = i / 40, q = i - j * 40;
            int src = g_src[g_csr_edge[cb + j]];
            ((float4*)xs[j])[q] = ((const float4*)(X + (size_t)src * HID))[q];
        }
        // stage h rows: m*32 floats
        for (int i = t; i < m * EH; i += 256) {
            int j = i >> 5, k = i & 31;
            hs[j][k] = g_h[slot][g_csr_edge[cb + j] * EH + k];
        }
        __syncthreads();
        for (int j = 0; j < m; j++) {
            #pragma unroll
            for (int r = 0; r < 20; r++)
                acc[r] += hs[j][kk[r]] * xs[j][ii[r]];
            if (t < HID) acc2 += xs[j][t];
        }
        __syncthreads();
    }

    float* Tr = g_T + (size_t)n * NCOLS;
    #pragma unroll
    for (int r = 0; r < 20; r++)
        Tr[kpos(t + 256 * r)] = __uint_as_float(f2tf32(inv * acc[r]));
    if (t < HID) {
        Tr[kpos(COL_B2 + t)]   = __uint_as_float(f2tf32(inv * acc2));
        Tr[kpos(COL_ROOT + t)] = __uint_as_float(f2tf32(X[(size_t)n * HID + t]));
    }
}

// =====================================================================
// Split-K TF32 GEMM: g_out[2048,160] += T[2048,5440] @ B[5440,160]
// grid (9 splits, 32 m-tiles) = 288 CTAs, 2 CTAs/SM -> one wave.
// CTA: 256 thr, BM=64, BN=160, BK=32; warps 2(M)x4(N) -> 32x40 each.
// =====================================================================
#define TS_STRIDE 40
#define WS_STRIDE 164
#define TS_ELEMS (64 * TS_STRIDE)    // 2560
#define WS_ELEMS (32 * WS_STRIDE)    // 5248
#define GEMM_SMEM ((TS_ELEMS + WS_ELEMS) * 2 * 4)   // 62464 B
#define K_UNITS (NCOLS / 32)         // 170
#define SPLITS 9

__device__ __forceinline__ void mma_tf32(float* d, const uint32_t* a, const uint32_t* b) {
    asm volatile(
        "mma.sync.aligned.m16n8k8.row.col.f32.tf32.tf32.f32 "
        "{%0,%1,%2,%3}, {%4,%5,%6,%7}, {%8,%9}, {%0,%1,%2,%3};"
        : "+f"(d[0]), "+f"(d[1]), "+f"(d[2]), "+f"(d[3])
        : "r"(a[0]), "r"(a[1]), "r"(a[2]), "r"(a[3]), "r"(b[0]), "r"(b[1]));
}

__global__ __launch_bounds__(256, 2) void gemm_kernel(int wslot) {
    const float* __restrict__ W = g_B[wslot];

    extern __shared__ float smem[];
    float* Ts = smem;
    float* Ws = smem + 2 * TS_ELEMS;

    int tid  = threadIdx.x;
    int lane = tid & 31;
    int w    = tid >> 5;
    int wm   = w & 1;          // 2 warps in M (32 rows each)
    int wn   = w >> 1;         // 4 warps in N (40 cols each)
    int g    = lane >> 2;
    int tig  = lane & 3;

    int m0    = blockIdx.y * 64;
    int split = blockIdx.x;
    int u0    = split * 19;                 // splits 0..7: 19 units; split 8: 18
    int cnt   = (split == 8) ? (K_UNITS - 8 * 19) : 19;

    float acc[2][5][4];
    #pragma unroll
    for (int i = 0; i < 2; i++)
        #pragma unroll
        for (int j = 0; j < 5; j++)
            #pragma unroll
            for (int r = 0; r < 4; r++) acc[i][j][r] = 0.0f;

    auto stage = [&](int buf, int ku) {
        int k0 = ku * 32;
        float* td = Ts + buf * TS_ELEMS;
        float* wd = Ws + buf * WS_ELEMS;
        #pragma unroll
        for (int i = 0; i < 2; i++) {
            int s   = tid + 256 * i;        // 0..511
            int row = s >> 3;
            int col = (s & 7) * 4;
            uint32_t dst = (uint32_t)__cvta_generic_to_shared(&td[row * TS_STRIDE + col]);
            const float* src = g_T + (size_t)(m0 + row) * NCOLS + k0 + col;
            asm volatile("cp.async.cg.shared.global [%0], [%1], 16;"
                         :: "r"(dst), "l"(src));
        }
        #pragma unroll
        for (int i = 0; i < 5; i++) {
            int s   = tid + 256 * i;        // 0..1279
            int row = s / 40;
            int col = (s % 40) * 4;
            uint32_t dst = (uint32_t)__cvta_generic_to_shared(&wd[row * WS_STRIDE + col]);
            const float* src = W + (size_t)(k0 + row) * HID + col;
            asm volatile("cp.async.cg.shared.global [%0], [%1], 16;"
                         :: "r"(dst), "l"(src));
        }
        asm volatile("cp.async.commit_group;");
    };

    stage(0, u0);

    for (int it = 0; it < cnt; it++) {
        if (it + 1 < cnt) {
            stage((it + 1) & 1, u0 + it + 1);
            asm volatile("cp.async.wait_group 1;");
        } else {
            asm volatile("cp.async.wait_group 0;");
        }
        __syncthreads();

        const uint32_t* ts = (const uint32_t*)(Ts + (it & 1) * TS_ELEMS);
        const uint32_t* ws = (const uint32_t*)(Ws + (it & 1) * WS_ELEMS);

        #pragma unroll
        for (int ks = 0; ks < 4; ks++) {
            int ck = ks * 8;
            uint32_t af[2][4];
            #pragma unroll
            for (int mt = 0; mt < 2; mt++) {
                int rb = wm * 32 + mt * 16;
                uint2 alo = *(const uint2*)&ts[(rb + g)     * TS_STRIDE + ck + 2 * tig];
                uint2 ahi = *(const uint2*)&ts[(rb + g + 8) * TS_STRIDE + ck + 2 * tig];
                af[mt][0] = alo.x;
                af[mt][1] = ahi.x;
                af[mt][2] = alo.y;
                af[mt][3] = ahi.y;
            }
            uint32_t bf[5][2];
            #pragma unroll
            for (int nt = 0; nt < 5; nt++) {
                int nc = wn * 40 + nt * 8 + g;
                bf[nt][0] = ws[(ck + 2 * tig)     * WS_STRIDE + nc];
                bf[nt][1] = ws[(ck + 2 * tig + 1) * WS_STRIDE + nc];
            }
            #pragma unroll
            for (int mt = 0; mt < 2; mt++)
                #pragma unroll
                for (int nt = 0; nt < 5; nt++)
                    mma_tf32(acc[mt][nt], af[mt], bf[nt]);
        }
        __syncthreads();
    }

    // split-K reduce via fp32 RED
    #pragma unroll
    for (int mt = 0; mt < 2; mt++) {
        int row = m0 + wm * 32 + mt * 16 + g;
        #pragma unroll
        for (int nt = 0; nt < 5; nt++) {
            int col = wn * 40 + nt * 8 + 2 * tig;
            atomicAdd(&g_out[row * HID + col],           acc[mt][nt][0]);
            atomicAdd(&g_out[row * HID + col + 1],       acc[mt][nt][1]);
            atomicAdd(&g_out[(row + 8) * HID + col],     acc[mt][nt][2]);
            atomicAdd(&g_out[(row + 8) * HID + col + 1], acc[mt][nt][3]);
        }
    }
}

// =====================================================================
// Finalize: v = g_out + bias (+relu); write dest; re-zero g_out.
// =====================================================================
__global__ void final_kernel(const float* __restrict__ bias, int outsel,
                             float* __restrict__ dout, int relu) {
    int idx = blockIdx.x * blockDim.x + threadIdx.x;
    if (idx >= N_NODES * HID) return;
    int o = idx % HID;
    float v = g_out[idx] + bias[o];
    if (relu) v = fmaxf(v, 0.0f);
    g_out[idx] = 0.0f;
    if (outsel == 2) dout[idx] = v;
    else             g_xb[outsel][idx] = v;
}

// =====================================================================
// launch
// =====================================================================
extern "C" void kernel_launch(void* const* d_in, const int* in_sizes, int n_in,
                              void* d_out, int out_size) {
    const float* x       = (const float*)d_in[0];
    const float* ea      = (const float*)d_in[1];
    const float* w1_a    = (const float*)d_in[2];
    const float* b1_a    = (const float*)d_in[3];
    const float* w2_a    = (const float*)d_in[4];
    const float* b2_a    = (const float*)d_in[5];
    const float* root_a  = (const float*)d_in[6];
    const float* bias_a  = (const float*)d_in[7];
    const float* w1_b    = (const float*)d_in[8];
    const float* b1_b    = (const float*)d_in[9];
    const float* w2_b    = (const float*)d_in[10];
    const float* b2_b    = (const float*)d_in[11];
    const float* root_b  = (const float*)d_in[12];
    const float* bias_b  = (const float*)d_in[13];
    const void*  eidx    = d_in[14];
    float* out = (float*)d_out;

    static int smem_set = 0;
    if (!smem_set) {
        cudaFuncSetAttribute(gemm_kernel,
                             cudaFuncAttributeMaxDynamicSharedMemorySize, GEMM_SMEM);
        smem_set = 1;
    }

    prep_kernel<<<1, 1024>>>(eidx);
    params_kernel<<<2 * GB_BLOCKS + 2 * H_BLOCKS + Z_BLOCKS, 256>>>(
        w2_a, b2_a, root_a, w2_b, b2_b, root_b, ea, w1_a, b1_a, w1_b, b1_b);

    dim3 ggrid(SPLITS, N_NODES / 64);    // (9, 32) = 288 CTAs
    int fb = (N_NODES * HID + 255) / 256;

    // layer 0 (params a), relu
    agg_kernel<<<N_NODES, 256>>>(x, -1, 0);
    gemm_kernel<<<ggrid, 256, GEMM_SMEM>>>(0);
    final_kernel<<<fb, 256>>>(bias_a, 0, out, 1);

    // layer 1 (params b), relu
    agg_kernel<<<N_NODES, 256>>>(nullptr, 0, 1);
    gemm_kernel<<<ggrid, 256, GEMM_SMEM>>>(1);
    final_kernel<<<fb, 256>>>(bias_b, 1, out, 1);

    // layer 2 (params b), no relu -> d_out
    agg_kernel<<<N_NODES, 256>>>(nullptr, 1, 1);
    gemm_kernel<<<ggrid, 256, GEMM_SMEM>>>(1);
    final_kernel<<<fb, 256>>>(bias_b, 2, out, 0);
}

// round 8
// speedup vs baseline: 1.2806x; 1.2806x over previous
#include <cuda_runtime.h>
#include <cstdint>

#define N_NODES 2048
#define N_EDGES 8192
#define EDGE_DIM 10
#define EH 32
#define HID 160
#define NW (HID*HID)                 // 25600
#define COL_B2 (EH*HID)              // 5120
#define COL_ROOT (EH*HID + HID)      // 5280
#define NCOLS (EH*HID + HID + HID)   // 5440

// k-dim permutation baked into storage: within each 8-block,
// orig k%8 = t (0..3)  -> pos 2t ;  k%8 = t+4 -> pos 2t+1.
__host__ __device__ __forceinline__ int kpos(int k) {
    return (k & ~7) | ((k & 3) << 1) | ((k & 4) >> 2);
}

// ---------------- device scratch ----------------
__device__ float g_A[2][HID * NCOLS];     // tf32 bits, rows k-permuted
__device__ float g_h[2][N_EDGES * EH];
__device__ float g_Y[N_NODES * NCOLS];
__device__ float g_accum[N_NODES * HID];
__device__ float g_x[2][N_NODES * HID];   // tf32 bits, cols k-permuted
__device__ int   g_cnt[N_NODES];
__device__ int   g_dst[N_EDGES];
__device__ int   g_csr_off[N_NODES + 1];
__device__ int   g_csr_edge[N_EDGES];

__device__ __forceinline__ uint32_t f2tf32(float f) {
    uint32_t u;
    asm("cvt.rna.tf32.f32 %0, %1;" : "=r"(u) : "f"(f));
    return u;
}

// =====================================================================
// Preprocessing (one block)
// =====================================================================
__global__ __launch_bounds__(1024) void prep_kernel(const void* __restrict__ eiraw) {
    __shared__ int s_flag;
    __shared__ int s_cs[N_NODES];
    __shared__ int s_cd[N_NODES];
    __shared__ int s_a[N_NODES];
    __shared__ int s_b[N_NODES];
    int t = threadIdx.x;

    for (int i = t; i < N_NODES; i += 1024) { s_cs[i] = 0; s_cd[i] = 0; }
    if (t == 0) s_flag = 0;
    __syncthreads();

    const int* raw = (const int*)eiraw;
    int f = 0;
    for (int i = t; i < N_EDGES; i += 1024)
        if (raw[2 * i + 1] != 0) f = 1;
    if (f) atomicOr(&s_flag, 1);
    __syncthreads();
    int flag = s_flag;

    int es[8], ed[8];
    #pragma unroll
    for (int j = 0; j < 8; j++) {
        int e = t + 1024 * j;
        if (flag) {
            es[j] = raw[e]; ed[j] = raw[N_EDGES + e];
        } else {
            const long long* p = (const long long*)eiraw;
            es[j] = (int)p[e]; ed[j] = (int)p[N_EDGES + e];
        }
        atomicAdd(&s_cs[es[j]], 1);
        atomicAdd(&s_cd[ed[j]], 1);
        g_dst[e] = ed[j];
    }
    __syncthreads();

    for (int i = t; i < N_NODES; i += 1024) { g_cnt[i] = s_cd[i]; s_a[i] = s_cs[i]; }
    __syncthreads();

    int* pa = s_a; int* pb = s_b;
    for (int d = 1; d < N_NODES; d <<= 1) {
        for (int i = t; i < N_NODES; i += 1024)
            pb[i] = pa[i] + (i >= d ? pa[i - d] : 0);
        __syncthreads();
        int* tmp = pa; pa = pb; pb = tmp;
    }
    for (int i = t; i < N_NODES; i += 1024) {
        int off = (i == 0) ? 0 : pa[i - 1];
        g_csr_off[i] = off;
        pb[i] = off;
    }
    if (t == 0) g_csr_off[N_NODES] = N_EDGES;
    __syncthreads();

    #pragma unroll
    for (int j = 0; j < 8; j++) {
        int e = t + 1024 * j;
        int pos = atomicAdd(&pb[es[j]], 1);
        g_csr_edge[pos] = e;
    }
}

// =====================================================================
// Params mega-kernel: build_A (tf32, row-permuted) + edge MLP h +
// zero accum + convert input x into g_x[1] (tf32, col-permuted).
// =====================================================================
#define NA_BLOCKS ((HID * NCOLS + 255) / 256)        // 3400
#define H_BLOCKS  (N_EDGES / 8)                      // 1024
#define Z_BLOCKS  ((N_NODES * HID + 255) / 256)      // 1280
#define XC_BLOCKS ((N_NODES * HID + 255) / 256)      // 1280

__global__ __launch_bounds__(256) void params_kernel(
        const float* __restrict__ w2a, const float* __restrict__ b2a,
        const float* __restrict__ roota,
        const float* __restrict__ w2b, const float* __restrict__ b2b,
        const float* __restrict__ rootb,
        const float* __restrict__ ea,
        const float* __restrict__ w1a, const float* __restrict__ b1a,
        const float* __restrict__ w1b, const float* __restrict__ b1b,
        const float* __restrict__ xin) {
    __shared__ float sw[EDGE_DIM * EH];
    __shared__ float sb[EH];
    int b = blockIdx.x;
    int t = threadIdx.x;

    if (b < 2 * NA_BLOCKS) {
        int slot = (b >= NA_BLOCKS);
        const float* w2   = slot ? w2b : w2a;
        const float* b2   = slot ? b2b : b2a;
        const float* root = slot ? rootb : roota;
        int idx = (b - slot * NA_BLOCKS) * 256 + t;
        if (idx < HID * NCOLS) {
            int i = idx / NCOLS;     // k-index (row)
            int c = idx % NCOLS;
            float v;
            if (c < COL_B2) {
                int k = c / HID, o = c % HID;
                v = w2[k * NW + i * HID + o];
            } else if (c < COL_ROOT) {
                v = b2[i * HID + (c - COL_B2)];
            } else {
                v = root[i * HID + (c - COL_ROOT)];
            }
            g_A[slot][kpos(i) * NCOLS + c] = __uint_as_float(f2tf32(v));
        }
    } else if (b < 2 * NA_BLOCKS + 2 * H_BLOCKS) {
        int bb = b - 2 * NA_BLOCKS;
        int slot = (bb >= H_BLOCKS);
        const float* w1 = slot ? w1b : w1a;
        const float* b1 = slot ? b1b : b1a;
        for (int i = t; i < EDGE_DIM * EH; i += 256) sw[i] = w1[i];
        if (t < EH) sb[t] = b1[t];
        __syncthreads();
        int j  = t & 31;
        int e  = (bb - slot * H_BLOCKS) * 8 + (t >> 5);
        float acc = sb[j];
        #pragma unroll
        for (int d = 0; d < EDGE_DIM; d++)
            acc += ea[e * EDGE_DIM + d] * sw[d * EH + j];
        g_h[slot][e * EH + j] = fmaxf(acc, 0.0f);
    } else if (b < 2 * NA_BLOCKS + 2 * H_BLOCKS + Z_BLOCKS) {
        int idx = (b - 2 * NA_BLOCKS - 2 * H_BLOCKS) * 256 + t;
        if (idx < N_NODES * HID) g_accum[idx] = 0.0f;
    } else {
        int idx = (b - 2 * NA_BLOCKS - 2 * H_BLOCKS - Z_BLOCKS) * 256 + t;
        if (idx < N_NODES * HID) {
            int n = idx / HID, o = idx % HID;
            g_x[1][n * HID + kpos(o)] = __uint_as_float(f2tf32(xin[idx]));
        }
    }
}

// =====================================================================
// TF32 GEMM (R5 config — best measured): cp.async double-buffered,
// pre-converted operands, k-permuted smem, LDS.64 A-fragments.
// =====================================================================
#define BM 128
#define BN 128
#define BK 32
#define AS_STRIDE 40
#define BS_STRIDE 132
#define AS_ELEMS (BM * AS_STRIDE)     // 5120
#define BS_ELEMS (BK * BS_STRIDE)     // 4224
#define GEMM_SMEM ((AS_ELEMS + BS_ELEMS) * 2 * 4)   // 74752 B

__device__ __forceinline__ void mma_tf32(float* d, const uint32_t* a, const uint32_t* b) {
    asm volatile(
        "mma.sync.aligned.m16n8k8.row.col.f32.tf32.tf32.f32 "
        "{%0,%1,%2,%3}, {%4,%5,%6,%7}, {%8,%9}, {%0,%1,%2,%3};"
        : "+f"(d[0]), "+f"(d[1]), "+f"(d[2]), "+f"(d[3])
        : "r"(a[0]), "r"(a[1]), "r"(a[2]), "r"(a[3]), "r"(b[0]), "r"(b[1]));
}

__global__ __launch_bounds__(256, 2) void gemm_kernel(int xsel, int aslot) {
    const float* __restrict__ X  = g_x[xsel];
    const float* __restrict__ Bm = g_A[aslot];

    extern __shared__ float smem[];
    float* As = smem;
    float* Bs = smem + 2 * AS_ELEMS;

    int tid  = threadIdx.x;
    int lane = tid & 31;
    int w    = tid >> 5;
    int wm   = w & 1;
    int wn   = w >> 1;
    int g    = lane >> 2;
    int tig  = lane & 3;

    int n0 = blockIdx.x * BN;
    int m0 = blockIdx.y * BM;

    float acc[4][4][4];
    #pragma unroll
    for (int i = 0; i < 4; i++)
        #pragma unroll
        for (int j = 0; j < 4; j++)
            #pragma unroll
            for (int r = 0; r < 4; r++) acc[i][j][r] = 0.0f;

    auto stage = [&](int buf, int k0) {
        float* ad = As + buf * AS_ELEMS;
        float* bd = Bs + buf * BS_ELEMS;
        #pragma unroll
        for (int i = 0; i < 4; i++) {
            int s   = tid + 256 * i;
            int row = s >> 3;
            int col = (s & 7) * 4;
            uint32_t dst = (uint32_t)__cvta_generic_to_shared(&ad[row * AS_STRIDE + col]);
            const float* src = X + (size_t)(m0 + row) * HID + k0 + col;
            asm volatile("cp.async.cg.shared.global [%0], [%1], 16;"
                         :: "r"(dst), "l"(src));
        }
        #pragma unroll
        for (int i = 0; i < 4; i++) {
            int s   = tid + 256 * i;
            int row = s >> 5;
            int col = (s & 31) * 4;
            int gc  = n0 + col;
            uint32_t dst = (uint32_t)__cvta_generic_to_shared(&bd[row * BS_STRIDE + col]);
            const float* src = Bm + (size_t)(k0 + row) * NCOLS + gc;
            int bytes = (gc < NCOLS) ? 16 : 0;
            asm volatile("cp.async.cg.shared.global [%0], [%1], 16, %2;"
                         :: "r"(dst), "l"(src), "r"(bytes));
        }
        asm volatile("cp.async.commit_group;");
    };

    stage(0, 0);

    for (int it = 0; it < 5; it++) {
        if (it < 4) {
            stage((it + 1) & 1, (it + 1) * BK);
            asm volatile("cp.async.wait_group 1;");
        } else {
            asm volatile("cp.async.wait_group 0;");
        }
        __syncthreads();

        const uint32_t* as = (const uint32_t*)(As + (it & 1) * AS_ELEMS);
        const uint32_t* bs = (const uint32_t*)(Bs + (it & 1) * BS_ELEMS);

        #pragma unroll
        for (int ks = 0; ks < 4; ks++) {
            int ck = ks * 8;
            uint32_t af[4][4];
            #pragma unroll
            for (int mt = 0; mt < 4; mt++) {
                int rb = wm * 64 + mt * 16;
                uint2 alo = *(const uint2*)&as[(rb + g)     * AS_STRIDE + ck + 2 * tig];
                uint2 ahi = *(const uint2*)&as[(rb + g + 8) * AS_STRIDE + ck + 2 * tig];
                af[mt][0] = alo.x;
                af[mt][1] = ahi.x;
                af[mt][2] = alo.y;
                af[mt][3] = ahi.y;
            }
            uint32_t bf[4][2];
            #pragma unroll
            for (int nt = 0; nt < 4; nt++) {
                int nc = wn * 32 + nt * 8 + g;
                bf[nt][0] = bs[(ck + 2 * tig)     * BS_STRIDE + nc];
                bf[nt][1] = bs[(ck + 2 * tig + 1) * BS_STRIDE + nc];
            }
            #pragma unroll
            for (int mt = 0; mt < 4; mt++)
                #pragma unroll
                for (int nt = 0; nt < 4; nt++)
                    mma_tf32(acc[mt][nt], af[mt], bf[nt]);
        }
        __syncthreads();
    }

    #pragma unroll
    for (int mt = 0; mt < 4; mt++) {
        int row = m0 + wm * 64 + mt * 16 + g;
        #pragma unroll
        for (int nt = 0; nt < 4; nt++) {
            int col = n0 + wn * 32 + nt * 8 + 2 * tig;
            if (col < NCOLS) {
                *(float2*)(g_Y + (size_t)row * NCOLS + col) =
                    make_float2(acc[mt][nt][0], acc[mt][nt][1]);
                *(float2*)(g_Y + (size_t)(row + 8) * NCOLS + col) =
                    make_float2(acc[mt][nt][2], acc[mt][nt][3]);
            }
        }
    }
}

// =====================================================================
// Edge message + scatter (R4 config — best measured: 256 thr, regs 32).
// CSR-by-src: Y row staged float4 once, flattened (edge,out) work.
// =====================================================================
#define ECHUNK 32

__global__ __launch_bounds__(256) void edge_kernel(int slot) {
    __shared__ float sY[COL_ROOT];          // 21120 B
    __shared__ float sh[ECHUNK * EH];       // 4096 B
    __shared__ int   sdst[ECHUNK];
    int n = blockIdx.x;
    int t = threadIdx.x;
    int beg = g_csr_off[n];
    int end = g_csr_off[n + 1];
    if (beg == end) return;

    const float4* Yr4 = (const float4*)(g_Y + (size_t)n * NCOLS);
    #pragma unroll
    for (int i = t; i < COL_ROOT / 4; i += 256)
        ((float4*)sY)[i] = Yr4[i];
    __syncthreads();

    for (int cb = beg; cb < end; cb += ECHUNK) {
        int m = min(end - cb, ECHUNK);
        for (int i = t; i < m * EH; i += 256) {
            int j = i >> 5, k = i & 31;
            int e = g_csr_edge[cb + j];
            sh[i] = g_h[slot][e * EH + k];
        }
        if (t < m) sdst[t] = g_dst[g_csr_edge[cb + t]];
        __syncthreads();
        for (int idx = t; idx < m * HID; idx += 256) {
            int j = idx / HID, o = idx - j * HID;
            const float* hj = &sh[j * EH];
            float msg = sY[COL_B2 + o];
            #pragma unroll
            for (int k = 0; k < EH; k++) msg += hj[k] * sY[k * HID + o];
            atomicAdd(&g_accum[sdst[j] * HID + o], msg);
        }
        __syncthreads();
    }
}

// =====================================================================
// Finalize. Intermediate layers write tf32-rounded, k-permuted features;
// last layer writes f32 d_out. Re-zeroes accum.
// =====================================================================
__global__ void final_kernel(const float* __restrict__ bias, int outsel,
                             float* __restrict__ dout, int relu) {
    int idx = blockIdx.x * blockDim.x + threadIdx.x;
    if (idx >= N_NODES * HID) return;
    int n = idx / HID, o = idx % HID;
    float inv = 1.0f / fmaxf((float)g_cnt[n], 1.0f);
    float v = g_accum[idx] * inv + g_Y[(size_t)n * NCOLS + COL_ROOT + o] + bias[o];
    if (relu) v = fmaxf(v, 0.0f);
    g_accum[idx] = 0.0f;
    if (outsel == 2) {
        dout[idx] = v;
    } else {
        g_x[outsel][n * HID + kpos(o)] = __uint_as_float(f2tf32(v));
    }
}

// =====================================================================
// launch
// =====================================================================
extern "C" void kernel_launch(void* const* d_in, const int* in_sizes, int n_in,
                              void* d_out, int out_size) {
    const float* x       = (const float*)d_in[0];
    const float* ea      = (const float*)d_in[1];
    const float* w1_a    = (const float*)d_in[2];
    const float* b1_a    = (const float*)d_in[3];
    const float* w2_a    = (const float*)d_in[4];
    const float* b2_a    = (const float*)d_in[5];
    const float* root_a  = (const float*)d_in[6];
    const float* bias_a  = (const float*)d_in[7];
    const float* w1_b    = (const float*)d_in[8];
    const float* b1_b    = (const float*)d_in[9];
    const float* w2_b    = (const float*)d_in[10];
    const float* b2_b    = (const float*)d_in[11];
    const float* root_b  = (const float*)d_in[12];
    const float* bias_b  = (const float*)d_in[13];
    const void*  eidx    = d_in[14];
    float* out = (float*)d_out;

    static int smem_set = 0;
    if (!smem_set) {
        cudaFuncSetAttribute(gemm_kernel,
                             cudaFuncAttributeMaxDynamicSharedMemorySize, GEMM_SMEM);
        smem_set = 1;
    }

    prep_kernel<<<1, 1024>>>(eidx);
    params_kernel<<<2 * NA_BLOCKS + 2 * H_BLOCKS + Z_BLOCKS + XC_BLOCKS, 256>>>(
        w2_a, b2_a, root_a, w2_b, b2_b, root_b, ea, w1_a, b1_a, w1_b, b1_b, x);

    dim3 gemm_grid((NCOLS + BN - 1) / BN, N_NODES / BM);   // (43, 16)
    int nh = N_NODES * HID;
    int fb = (nh + 255) / 256;

    // layer 0 (params a), relu — converted input lives in g_x[1]
    gemm_kernel<<<gemm_grid, 256, GEMM_SMEM>>>(1, 0);
    edge_kernel<<<N_NODES, 256>>>(0);
    final_kernel<<<fb, 256>>>(bias_a, 0, out, 1);

    // layer 1 (params b), relu
    gemm_kernel<<<gemm_grid, 256, GEMM_SMEM>>>(0, 1);
    edge_kernel<<<N_NODES, 256>>>(1);
    final_kernel<<<fb, 256>>>(bias_b, 1, out, 1);

    // layer 2 (params b), no relu -> d_out
    gemm_kernel<<<gemm_grid, 256, GEMM_SMEM>>>(1, 1);
    edge_kernel<<<N_NODES, 256>>>(1);
    final_kernel<<<fb, 256>>>(bias_b, 2, out, 0);
}

// round 9
// speedup vs baseline: 1.6096x; 1.2569x over previous
#include <cuda_runtime.h>
#include <cuda_fp16.h>
#include <cstdint>

#define N_NODES 2048
#define N_EDGES 8192
#define EDGE_DIM 10
#define EH 32
#define HID 160
#define NW (HID*HID)                 // 25600
#define COL_B2 (EH*HID)              // 5120
#define COL_ROOT (EH*HID + HID)      // 5280
#define NCOLS (EH*HID + HID + HID)   // 5440
#define NROWS_PAD 5504               // NCOLS padded to 128 multiple

// fp16 k-permutation within 16-blocks: thread tig reads orig k
// {2t,2t+1,8+2t,8+2t+1} as 4 contiguous halves at pos 4t..4t+3.
__host__ __device__ __forceinline__ int kp16(int k) {
    return (k & ~15) | (((k & 7) >> 1) << 2) | ((k & 8) >> 2) | (k & 1);
}

// ---------------- device scratch ----------------
__device__ __half g_At[2][NROWS_PAD * HID];     // W^T [n][k], kp16 cols, fp16
__device__ __half g_x[2][N_NODES * HID];        // features, kp16 cols, fp16
__device__ __half g_Yh[(size_t)N_NODES * COL_ROOT]; // Y msg+b2 cols, fp16
__device__ float  g_Yroot[N_NODES * HID];       // Y root cols, fp32
__device__ float  g_h[2][N_EDGES * EH];
__device__ float  g_accum[N_NODES * HID];
__device__ int    g_cnt[N_NODES];
__device__ int    g_dst[N_EDGES];
__device__ int    g_csr_off[N_NODES + 1];
__device__ int    g_csr_edge[N_EDGES];

// =====================================================================
// Preprocessing (one block)
// =====================================================================
__global__ __launch_bounds__(1024) void prep_kernel(const void* __restrict__ eiraw) {
    __shared__ int s_flag;
    __shared__ int s_cs[N_NODES];
    __shared__ int s_cd[N_NODES];
    __shared__ int s_a[N_NODES];
    __shared__ int s_b[N_NODES];
    int t = threadIdx.x;

    for (int i = t; i < N_NODES; i += 1024) { s_cs[i] = 0; s_cd[i] = 0; }
    if (t == 0) s_flag = 0;
    __syncthreads();

    const int* raw = (const int*)eiraw;
    int f = 0;
    for (int i = t; i < N_EDGES; i += 1024)
        if (raw[2 * i + 1] != 0) f = 1;
    if (f) atomicOr(&s_flag, 1);
    __syncthreads();
    int flag = s_flag;

    int es[8], ed[8];
    #pragma unroll
    for (int j = 0; j < 8; j++) {
        int e = t + 1024 * j;
        if (flag) {
            es[j] = raw[e]; ed[j] = raw[N_EDGES + e];
        } else {
            const long long* p = (const long long*)eiraw;
            es[j] = (int)p[e]; ed[j] = (int)p[N_EDGES + e];
        }
        atomicAdd(&s_cs[es[j]], 1);
        atomicAdd(&s_cd[ed[j]], 1);
        g_dst[e] = ed[j];
    }
    __syncthreads();

    for (int i = t; i < N_NODES; i += 1024) { g_cnt[i] = s_cd[i]; s_a[i] = s_cs[i]; }
    __syncthreads();

    int* pa = s_a; int* pb = s_b;
    for (int d = 1; d < N_NODES; d <<= 1) {
        for (int i = t; i < N_NODES; i += 1024)
            pb[i] = pa[i] + (i >= d ? pa[i - d] : 0);
        __syncthreads();
        int* tmp = pa; pa = pb; pb = tmp;
    }
    for (int i = t; i < N_NODES; i += 1024) {
        int off = (i == 0) ? 0 : pa[i - 1];
        g_csr_off[i] = off;
        pb[i] = off;
    }
    if (t == 0) g_csr_off[N_NODES] = N_EDGES;
    __syncthreads();

    #pragma unroll
    for (int j = 0; j < 8; j++) {
        int e = t + 1024 * j;
        int pos = atomicAdd(&pb[es[j]], 1);
        g_csr_edge[pos] = e;
    }
}

// =====================================================================
// Params mega-kernel: build g_At (fp16 transposed weights, kp16 cols)
// + edge MLP h + zero accum + convert x into g_x[1].
// =====================================================================
#define AT_BLOCKS (NROWS_PAD * HID / 256)            // 3440
#define H_BLOCKS  (N_EDGES / 8)                      // 1024
#define Z_BLOCKS  (N_NODES * HID / 256)              // 1280
#define XC_BLOCKS (N_NODES * HID / 256)              // 1280

__global__ __launch_bounds__(256) void params_kernel(
        const float* __restrict__ w2a, const float* __restrict__ b2a,
        const float* __restrict__ roota,
        const float* __restrict__ w2b, const float* __restrict__ b2b,
        const float* __restrict__ rootb,
        const float* __restrict__ ea,
        const float* __restrict__ w1a, const float* __restrict__ b1a,
        const float* __restrict__ w1b, const float* __restrict__ b1b,
        const float* __restrict__ xin) {
    __shared__ float sw[EDGE_DIM * EH];
    __shared__ float sb[EH];
    int b = blockIdx.x;
    int t = threadIdx.x;

    if (b < 2 * AT_BLOCKS) {
        int slot = (b >= AT_BLOCKS);
        const float* w2   = slot ? w2b : w2a;
        const float* b2   = slot ? b2b : b2a;
        const float* root = slot ? rootb : roota;
        int idx = (b - slot * AT_BLOCKS) * 256 + t;   // < 880640
        int c = idx / HID;      // output row (n-dim), 0..5503
        int k = idx % HID;      // k-dim
        float v = 0.0f;
        if (c < COL_B2)        v = w2[(c / HID) * NW + k * HID + (c % HID)];
        else if (c < COL_ROOT) v = b2[k * HID + (c - COL_B2)];
        else if (c < NCOLS)    v = root[k * HID + (c - COL_ROOT)];
        g_At[slot][c * HID + kp16(k)] = __float2half_rn(v);
    } else if (b < 2 * AT_BLOCKS + 2 * H_BLOCKS) {
        int bb = b - 2 * AT_BLOCKS;
        int slot = (bb >= H_BLOCKS);
        const float* w1 = slot ? w1b : w1a;
        const float* b1 = slot ? b1b : b1a;
        for (int i = t; i < EDGE_DIM * EH; i += 256) sw[i] = w1[i];
        if (t < EH) sb[t] = b1[t];
        __syncthreads();
        int j  = t & 31;
        int e  = (bb - slot * H_BLOCKS) * 8 + (t >> 5);
        float acc = sb[j];
        #pragma unroll
        for (int d = 0; d < EDGE_DIM; d++)
            acc += ea[e * EDGE_DIM + d] * sw[d * EH + j];
        g_h[slot][e * EH + j] = fmaxf(acc, 0.0f);
    } else if (b < 2 * AT_BLOCKS + 2 * H_BLOCKS + Z_BLOCKS) {
        int idx = (b - 2 * AT_BLOCKS - 2 * H_BLOCKS) * 256 + t;
        g_accum[idx] = 0.0f;
    } else {
        int idx = (b - 2 * AT_BLOCKS - 2 * H_BLOCKS - Z_BLOCKS) * 256 + t;
        int n = idx / HID, o = idx % HID;
        g_x[1][n * HID + kp16(o)] = __float2half_rn(xin[idx]);
    }
}

// =====================================================================
// FP16 tensor GEMM: Y[2048,5440] = X[2048,160] @ W[160,5440]
// mma.m16n8k16.f16 (f32 accum). A = X [m][k] fp16; B = g_At [n][k] fp16.
// CTA 128x128, BK=32, double-buffered cp.async. No staging predicates
// (g_At padded to 5504 rows).
// =====================================================================
#define BM 128
#define BN 128
#define BK 32
#define SHS 48                        // smem row stride in halves (24 words)
#define ATILE (BM * SHS)              // 6144 halves per buffer
#define GEMM_SMEM (4 * ATILE * 2)     // 49152 B  (2 arrays x 2 buffers)

__device__ __forceinline__ void mma_f16(float* d, const uint32_t* a, const uint32_t* b) {
    asm volatile(
        "mma.sync.aligned.m16n8k16.row.col.f32.f16.f16.f32 "
        "{%0,%1,%2,%3}, {%4,%5,%6,%7}, {%8,%9}, {%0,%1,%2,%3};"
        : "+f"(d[0]), "+f"(d[1]), "+f"(d[2]), "+f"(d[3])
        : "r"(a[0]), "r"(a[1]), "r"(a[2]), "r"(a[3]), "r"(b[0]), "r"(b[1]));
}

__global__ __launch_bounds__(256, 2) void gemm_kernel(int xsel, int aslot) {
    const __half* __restrict__ X = g_x[xsel];
    const __half* __restrict__ W = g_At[aslot];

    extern __shared__ char smem_raw[];
    __half* As = (__half*)smem_raw;            // [2][ATILE]
    __half* Bs = As + 2 * ATILE;               // [2][ATILE]

    int tid  = threadIdx.x;
    int lane = tid & 31;
    int w    = tid >> 5;
    int wm   = w & 1;          // 2 warps in M (64 rows)
    int wn   = w >> 1;         // 4 warps in N (32 cols)
    int g    = lane >> 2;
    int tig  = lane & 3;

    int n0 = blockIdx.x * BN;
    int m0 = blockIdx.y * BM;

    float acc[4][4][4];
    #pragma unroll
    for (int i = 0; i < 4; i++)
        #pragma unroll
        for (int j = 0; j < 4; j++)
            #pragma unroll
            for (int r = 0; r < 4; r++) acc[i][j][r] = 0.0f;

    auto stage = [&](int buf, int k0) {
        __half* ad = As + buf * ATILE;
        __half* bd = Bs + buf * ATILE;
        #pragma unroll
        for (int i = 0; i < 2; i++) {
            int s   = tid + 256 * i;          // 0..511
            int row = s >> 2;
            int ch  = (s & 3) * 8;            // 8-half (16B) chunks
            uint32_t dst = (uint32_t)__cvta_generic_to_shared(&ad[row * SHS + ch]);
            const __half* src = X + (size_t)(m0 + row) * HID + k0 + ch;
            asm volatile("cp.async.cg.shared.global [%0], [%1], 16;"
                         :: "r"(dst), "l"(src));
        }
        #pragma unroll
        for (int i = 0; i < 2; i++) {
            int s   = tid + 256 * i;
            int row = s >> 2;
            int ch  = (s & 3) * 8;
            uint32_t dst = (uint32_t)__cvta_generic_to_shared(&bd[row * SHS + ch]);
            const __half* src = W + (size_t)(n0 + row) * HID + k0 + ch;
            asm volatile("cp.async.cg.shared.global [%0], [%1], 16;"
                         :: "r"(dst), "l"(src));
        }
        asm volatile("cp.async.commit_group;");
    };

    stage(0, 0);

    for (int it = 0; it < 5; it++) {
        if (it < 4) {
            stage((it + 1) & 1, (it + 1) * BK);
            asm volatile("cp.async.wait_group 1;");
        } else {
            asm volatile("cp.async.wait_group 0;");
        }
        __syncthreads();

        const __half* as = As + (it & 1) * ATILE;
        const __half* bs = Bs + (it & 1) * ATILE;

        #pragma unroll
        for (int ks = 0; ks < 2; ks++) {
            int ck = ks * 16;
            uint32_t af[4][4];
            #pragma unroll
            for (int mt = 0; mt < 4; mt++) {
                int rb = wm * 64 + mt * 16;
                uint2 lo = *(const uint2*)&as[(rb + g)     * SHS + ck + 4 * tig];
                uint2 hi = *(const uint2*)&as[(rb + g + 8) * SHS + ck + 4 * tig];
                af[mt][0] = lo.x;   // (row g,   k 2t..2t+1)
                af[mt][1] = hi.x;   // (row g+8, k 2t..2t+1)
                af[mt][2] = lo.y;   // (row g,   k 2t+8..+9)
                af[mt][3] = hi.y;   // (row g+8, k 2t+8..+9)
            }
            uint32_t bf[4][2];
            #pragma unroll
            for (int nt = 0; nt < 4; nt++) {
                int nc = wn * 32 + nt * 8 + g;
                uint2 bb = *(const uint2*)&bs[nc * SHS + ck + 4 * tig];
                bf[nt][0] = bb.x;   // (k 2t..2t+1,  col g)
                bf[nt][1] = bb.y;   // (k 2t+8..+9,  col g)
            }
            #pragma unroll
            for (int mt = 0; mt < 4; mt++)
                #pragma unroll
                for (int nt = 0; nt < 4; nt++)
                    mma_f16(acc[mt][nt], af[mt], bf[nt]);
        }
        __syncthreads();
    }

    // epilogue: msg/b2 cols -> fp16 g_Yh; root cols -> fp32 g_Yroot
    #pragma unroll
    for (int mt = 0; mt < 4; mt++) {
        int row = m0 + wm * 64 + mt * 16 + g;
        #pragma unroll
        for (int nt = 0; nt < 4; nt++) {
            int col = n0 + wn * 32 + nt * 8 + 2 * tig;
            if (col < COL_ROOT) {
                *(__half2*)&g_Yh[(size_t)row * COL_ROOT + col] =
                    __floats2half2_rn(acc[mt][nt][0], acc[mt][nt][1]);
                *(__half2*)&g_Yh[(size_t)(row + 8) * COL_ROOT + col] =
                    __floats2half2_rn(acc[mt][nt][2], acc[mt][nt][3]);
            } else if (col < NCOLS) {
                int rc = col - COL_ROOT;
                *(float2*)&g_Yroot[row * HID + rc] =
                    make_float2(acc[mt][nt][0], acc[mt][nt][1]);
                *(float2*)&g_Yroot[(row + 8) * HID + rc] =
                    make_float2(acc[mt][nt][2], acc[mt][nt][3]);
            }
        }
    }
}

// =====================================================================
// Edge message + scatter (R4 structure; Y staged from fp16).
// =====================================================================
#define ECHUNK 32

__global__ __launch_bounds__(256) void edge_kernel(int slot) {
    __shared__ float sY[COL_ROOT];          // 21120 B
    __shared__ float sh[ECHUNK * EH];       // 4096 B
    __shared__ int   sdst[ECHUNK];
    int n = blockIdx.x;
    int t = threadIdx.x;
    int beg = g_csr_off[n];
    int end = g_csr_off[n + 1];
    if (beg == end) return;

    const __half2* Yr2 = (const __half2*)(g_Yh + (size_t)n * COL_ROOT);
    for (int i = t; i < COL_ROOT / 2; i += 256)
        ((float2*)sY)[i] = __half22float2(Yr2[i]);
    __syncthreads();

    for (int cb = beg; cb < end; cb += ECHUNK) {
        int m = min(end - cb, ECHUNK);
        for (int i = t; i < m * EH; i += 256) {
            int j = i >> 5, k = i & 31;
            int e = g_csr_edge[cb + j];
            sh[i] = g_h[slot][e * EH + k];
        }
        if (t < m) sdst[t] = g_dst[g_csr_edge[cb + t]];
        __syncthreads();
        for (int idx = t; idx < m * HID; idx += 256) {
            int j = idx / HID, o = idx - j * HID;
            const float* hj = &sh[j * EH];
            float msg = sY[COL_B2 + o];
            #pragma unroll
            for (int k = 0; k < EH; k++) msg += hj[k] * sY[k * HID + o];
            atomicAdd(&g_accum[sdst[j] * HID + o], msg);
        }
        __syncthreads();
    }
}

// =====================================================================
// Finalize: v = accum/max(cnt,1) + root(fp32) + bias; re-zero accum.
// Intermediate layers -> g_x fp16 (kp16); last -> fp32 d_out.
// =====================================================================
__global__ void final_kernel(const float* __restrict__ bias, int outsel,
                             float* __restrict__ dout, int relu) {
    int idx = blockIdx.x * blockDim.x + threadIdx.x;
    if (idx >= N_NODES * HID) return;
    int n = idx / HID, o = idx % HID;
    float inv = 1.0f / fmaxf((float)g_cnt[n], 1.0f);
    float v = g_accum[idx] * inv + g_Yroot[idx] + bias[o];
    if (relu) v = fmaxf(v, 0.0f);
    g_accum[idx] = 0.0f;
    if (outsel == 2) {
        dout[idx] = v;
    } else {
        g_x[outsel][n * HID + kp16(o)] = __float2half_rn(v);
    }
}

// =====================================================================
// launch
// =====================================================================
extern "C" void kernel_launch(void* const* d_in, const int* in_sizes, int n_in,
                              void* d_out, int out_size) {
    const float* x       = (const float*)d_in[0];
    const float* ea      = (const float*)d_in[1];
    const float* w1_a    = (const float*)d_in[2];
    const float* b1_a    = (const float*)d_in[3];
    const float* w2_a    = (const float*)d_in[4];
    const float* b2_a    = (const float*)d_in[5];
    const float* root_a  = (const float*)d_in[6];
    const float* bias_a  = (const float*)d_in[7];
    const float* w1_b    = (const float*)d_in[8];
    const float* b1_b    = (const float*)d_in[9];
    const float* w2_b    = (const float*)d_in[10];
    const float* b2_b    = (const float*)d_in[11];
    const float* root_b  = (const float*)d_in[12];
    const float* bias_b  = (const float*)d_in[13];
    const void*  eidx    = d_in[14];
    float* out = (float*)d_out;

    static int smem_set = 0;
    if (!smem_set) {
        cudaFuncSetAttribute(gemm_kernel,
                             cudaFuncAttributeMaxDynamicSharedMemorySize, GEMM_SMEM);
        smem_set = 1;
    }

    prep_kernel<<<1, 1024>>>(eidx);
    params_kernel<<<2 * AT_BLOCKS + 2 * H_BLOCKS + Z_BLOCKS + XC_BLOCKS, 256>>>(
        w2_a, b2_a, root_a, w2_b, b2_b, root_b, ea, w1_a, b1_a, w1_b, b1_b, x);

    dim3 gemm_grid((NCOLS + BN - 1) / BN, N_NODES / BM);   // (43, 16)
    int fb = (N_NODES * HID + 255) / 256;

    // layer 0 (params a), relu — converted input lives in g_x[1]
    gemm_kernel<<<gemm_grid, 256, GEMM_SMEM>>>(1, 0);
    edge_kernel<<<N_NODES, 256>>>(0);
    final_kernel<<<fb, 256>>>(bias_a, 0, out, 1);

    // layer 1 (params b), relu
    gemm_kernel<<<gemm_grid, 256, GEMM_SMEM>>>(0, 1);
    edge_kernel<<<N_NODES, 256>>>(1);
    final_kernel<<<fb, 256>>>(bias_b, 1, out, 1);

    // layer 2 (params b), no relu -> d_out
    gemm_kernel<<<gemm_grid, 256, GEMM_SMEM>>>(1, 1);
    edge_kernel<<<N_NODES, 256>>>(1);
    final_kernel<<<fb, 256>>>(bias_b, 2, out, 0);
}